// round 12
// baseline (speedup 1.0000x reference)
#include <cuda_runtime.h>
#include <cuda_bf16.h>

// FeaturesLinear: out[seg] = sum_t (weight[ids[t]] * ratings[t]) + bias
// ids: int32[N], ratings: f32[N], segs: int32[N] (sorted), weight: f32[V,16],
// bias: f32[16], out: f32[batch,16].  N = 819200.
//
// Single fused kernel: blocks 0..INIT_BLOCKS-1 initialize out=bias, then all
// blocks gather; flushes wait (acquire spin) for init completion. Counters
// self-reset each replay => deterministic + graph-capturable.

#define DIM 16
#define T_PER_THREAD 4
#define INIT_BLOCKS 256   // 256 blocks * 256 threads = 65536 float4 = out size

__device__ int g_init_done = 0;   // arrivals of init blocks
__device__ int g_blocks_fin = 0;  // arrivals of all blocks (for reset)

__device__ __forceinline__ float4 ldg_wt(const float4* p, unsigned long long pol) {
    float4 v;
    asm("ld.global.nc.L2::cache_hint.v4.f32 {%0,%1,%2,%3}, [%4], %5;"
        : "=f"(v.x), "=f"(v.y), "=f"(v.z), "=f"(v.w)
        : "l"(p), "l"(pol));
    return v;
}
__device__ __forceinline__ int4 ldg_meta_i4(const int4* p, unsigned long long pol) {
    int4 v;
    asm("ld.global.nc.L2::cache_hint.v4.u32 {%0,%1,%2,%3}, [%4], %5;"
        : "=r"(v.x), "=r"(v.y), "=r"(v.z), "=r"(v.w)
        : "l"(p), "l"(pol));
    return v;
}
__device__ __forceinline__ float4 ldg_meta_f4(const float4* p, unsigned long long pol) {
    float4 v;
    asm("ld.global.nc.L2::cache_hint.v4.f32 {%0,%1,%2,%3}, [%4], %5;"
        : "=f"(v.x), "=f"(v.y), "=f"(v.z), "=f"(v.w)
        : "l"(p), "l"(pol));
    return v;
}
__device__ __forceinline__ void red_add_v4(float* o, float4 v) {
    asm volatile("red.global.v4.f32.add [%0], {%1,%2,%3,%4};"
                 :: "l"(o), "f"(v.x), "f"(v.y), "f"(v.z), "f"(v.w) : "memory");
}

__global__ __launch_bounds__(256)
void fl_fused(const int*    __restrict__ ids,
              const float*  __restrict__ ratings,
              const int*    __restrict__ segs,
              const float4* __restrict__ weight4,
              const float4* __restrict__ bias4,
              float4*       __restrict__ out4,
              int n, int quads, int gridTotal) {
    const int bid = blockIdx.x;

    // ---------- phase 0: init blocks write out = bias ----------
    if (bid < INIT_BLOCKS) {
        int i = bid * 256 + (int)threadIdx.x;
        if (i < quads) out4[i] = __ldg(&bias4[i & 3]);
        __threadfence();                    // release init stores gpu-wide
        __syncthreads();
        if (threadIdx.x == 0) atomicAdd(&g_init_done, 1);
    }

    // ---------- phase 1: gather + accumulate ----------
    const int lane     = threadIdx.x & 31;
    const int slot     = lane & 3;
    const int tokGroup = lane >> 2;
    const int warpId   = bid * (blockDim.x >> 5) + (threadIdx.x >> 5);
    const int base     = warpId * 32 + tokGroup * T_PER_THREAD;
    const bool active  = (base < n);

    unsigned long long polWt, polMeta;
    asm("createpolicy.fractional.L2::evict_last.b64 %0, 0.75;"  : "=l"(polWt));
    asm("createpolicy.fractional.L2::evict_first.b64 %0, 1.0;" : "=l"(polMeta));

    int id[4]; float r[4]; int sg[4];
    float4 w[4];
    if (active) {
        int4   idv = ldg_meta_i4((const int4*)  (ids     + base), polMeta);
        float4 rv  = ldg_meta_f4((const float4*)(ratings + base), polMeta);
        int4   sv  = ldg_meta_i4((const int4*)  (segs    + base), polMeta);
        id[0]=idv.x; id[1]=idv.y; id[2]=idv.z; id[3]=idv.w;
        r[0]=rv.x; r[1]=rv.y; r[2]=rv.z; r[3]=rv.w;
        sg[0]=sv.x; sg[1]=sv.y; sg[2]=sv.z; sg[3]=sv.w;
        #pragma unroll
        for (int k = 0; k < T_PER_THREAD; k++)
            w[k] = ldg_wt(&weight4[(size_t)id[k] * 4 + slot], polWt);
    }

    // ---------- wait for init (hidden under gather latency) ----------
    if (threadIdx.x == 0) {
        int v;
        do {
            asm volatile("ld.acquire.gpu.global.b32 %0, [%1];"
                         : "=r"(v) : "l"(&g_init_done));
        } while (v < INIT_BLOCKS);
    }
    __syncthreads();

    if (active) {
        float* out = (float*)out4;

        float4 acc;
        acc.x = w[0].x * r[0]; acc.y = w[0].y * r[0];
        acc.z = w[0].z * r[0]; acc.w = w[0].w * r[0];

        #pragma unroll
        for (int k = 1; k < T_PER_THREAD; k++) {
            if (sg[k] != sg[k - 1]) {
                red_add_v4(out + (size_t)sg[k - 1] * DIM + slot * 4, acc);
                acc.x = acc.y = acc.z = acc.w = 0.f;
            }
            acc.x += w[k].x * r[k]; acc.y += w[k].y * r[k];
            acc.z += w[k].z * r[k]; acc.w += w[k].w * r[k];
        }

        // Cross-lane segmented suffix reduction on trailing partials
        // (keys monotone across the warp => exact).
        int seg = sg[T_PER_THREAD - 1];
        #pragma unroll
        for (int off = 4; off <= 16; off <<= 1) {
            int   oseg = __shfl_down_sync(0xffffffffu, seg, off);
            float ox   = __shfl_down_sync(0xffffffffu, acc.x, off);
            float oy   = __shfl_down_sync(0xffffffffu, acc.y, off);
            float oz   = __shfl_down_sync(0xffffffffu, acc.z, off);
            float ow   = __shfl_down_sync(0xffffffffu, acc.w, off);
            if ((lane + off) < 32 && oseg == seg) {
                acc.x += ox; acc.y += oy; acc.z += oz; acc.w += ow;
            }
        }
        const int  pseg = __shfl_up_sync(0xffffffffu, seg, 4);
        const bool head = (tokGroup == 0) || (pseg != seg);
        if (head)
            red_add_v4(out + (size_t)seg * DIM + slot * 4, acc);
    }

    // ---------- reset protocol: last block zeroes the counters ----------
    __syncthreads();
    if (threadIdx.x == 0) {
        __threadfence();
        int old = atomicAdd(&g_blocks_fin, 1);
        if (old == gridTotal - 1) {
            g_init_done  = 0;   // next replay sees pristine state
            g_blocks_fin = 0;
            __threadfence();
        }
    }
}

extern "C" void kernel_launch(void* const* d_in, const int* in_sizes, int n_in,
                              void* d_out, int out_size) {
    const int*   ids     = (const int*)  d_in[0];
    const float* ratings = (const float*)d_in[1];
    const int*   segs    = (const int*)  d_in[2];
    // d_in[3] = batch_size scalar (unused)
    const float* weight  = (const float*)d_in[4];
    const float* bias    = (const float*)d_in[5];

    const int n     = in_sizes[0];
    const int quads = out_size / 4;

    // Gather coverage: 32 tokens per warp, 8 warps per block.
    int warps  = (n + 31) / 32;
    int blocks = (warps + 7) / 8;
    if (blocks < INIT_BLOCKS) blocks = INIT_BLOCKS;   // init coverage guarantee

    fl_fused<<<blocks, 256>>>(ids, ratings, segs,
                              (const float4*)weight, (const float4*)bias,
                              (float4*)d_out, n, quads, blocks);
}

// round 13
// speedup vs baseline: 1.3409x; 1.3409x over previous
#include <cuda_runtime.h>
#include <cuda_bf16.h>

// FeaturesLinear: out[seg] = sum_t (weight[ids[t]] * ratings[t]) + bias
// ids: int32[N], ratings: f32[N], segs: int32[N] (sorted), weight: f32[V,16],
// bias: f32[16], out: f32[batch,16].  N = 819200 (multiple of 32).

#define DIM 16
#define T_PER_THREAD 4   // tokens per thread

__device__ __forceinline__ float4 ldg_wt(const float4* p, unsigned long long pol) {
    float4 v;
    asm("ld.global.nc.L2::cache_hint.v4.f32 {%0,%1,%2,%3}, [%4], %5;"
        : "=f"(v.x), "=f"(v.y), "=f"(v.z), "=f"(v.w)
        : "l"(p), "l"(pol));
    return v;
}
__device__ __forceinline__ int4 ldg_meta_i4(const int4* p, unsigned long long pol) {
    int4 v;
    asm("ld.global.nc.L2::cache_hint.v4.u32 {%0,%1,%2,%3}, [%4], %5;"
        : "=r"(v.x), "=r"(v.y), "=r"(v.z), "=r"(v.w)
        : "l"(p), "l"(pol));
    return v;
}
__device__ __forceinline__ float4 ldg_meta_f4(const float4* p, unsigned long long pol) {
    float4 v;
    asm("ld.global.nc.L2::cache_hint.v4.f32 {%0,%1,%2,%3}, [%4], %5;"
        : "=f"(v.x), "=f"(v.y), "=f"(v.z), "=f"(v.w)
        : "l"(p), "l"(pol));
    return v;
}
// One-instruction float4 global reduction (sm_100+).
__device__ __forceinline__ void red_add_v4(float* o, float4 v) {
    asm volatile("red.global.v4.f32.add [%0], {%1,%2,%3,%4};"
                 :: "l"(o), "f"(v.x), "f"(v.y), "f"(v.z), "f"(v.w) : "memory");
}

__global__ void fl_init_out(float4* __restrict__ out,
                            const float4* __restrict__ bias4,
                            int out_quads) {
    int i = blockIdx.x * blockDim.x + threadIdx.x;
    if (i < out_quads) out[i] = __ldg(&bias4[i & 3]);
}

// Lane layout: slot = lane & 3 (which float4 of the 16-float row),
// tokGroup = lane >> 2 (0..7). Thread handles 4 consecutive tokens;
// a warp covers 32 consecutive tokens.
__global__ __launch_bounds__(512)
void fl_main(const int*   __restrict__ ids,
             const float* __restrict__ ratings,
             const int*   __restrict__ segs,
             const float4* __restrict__ weight4,
             float*       __restrict__ out,
             int n) {
    const int lane     = threadIdx.x & 31;
    const int slot     = lane & 3;
    const int tokGroup = lane >> 2;
    const int warpsPerBlock = blockDim.x >> 5;
    const int warpId   = blockIdx.x * warpsPerBlock + (threadIdx.x >> 5);

    const int base = warpId * 32 + tokGroup * T_PER_THREAD;
    if (base >= n) return;

    unsigned long long polWt, polMeta;
    asm("createpolicy.fractional.L2::evict_last.b64 %0, 0.75;"  : "=l"(polWt));
    asm("createpolicy.fractional.L2::evict_first.b64 %0, 1.0;" : "=l"(polMeta));

    // ---- ids first: fire the long-latency row gathers immediately
    int4 idv = ldg_meta_i4((const int4*)(ids + base), polMeta);
    const int id[4] = {idv.x, idv.y, idv.z, idv.w};

    float4 w[4];
    #pragma unroll
    for (int k = 0; k < T_PER_THREAD; k++)
        w[k] = ldg_wt(&weight4[(size_t)id[k] * 4 + slot], polWt);

    // ---- remaining metadata loads overlap the gathers
    float4 rv = ldg_meta_f4((const float4*)(ratings + base), polMeta);
    int4   sv = ldg_meta_i4((const int4*)  (segs    + base), polMeta);
    const float r [4] = {rv.x, rv.y, rv.z, rv.w};
    const int   sg[4] = {sv.x, sv.y, sv.z, sv.w};

    // ---- thread-serial accumulation with flush on segment boundary
    float4 acc;
    acc.x = w[0].x * r[0]; acc.y = w[0].y * r[0];
    acc.z = w[0].z * r[0]; acc.w = w[0].w * r[0];

    #pragma unroll
    for (int k = 1; k < T_PER_THREAD; k++) {
        if (sg[k] != sg[k - 1]) {
            red_add_v4(out + (size_t)sg[k - 1] * DIM + slot * 4, acc);
            acc.x = acc.y = acc.z = acc.w = 0.f;
        }
        acc.x += w[k].x * r[k]; acc.y += w[k].y * r[k];
        acc.z += w[k].z * r[k]; acc.w += w[k].w * r[k];
    }

    // ---- cross-lane segmented suffix reduction on trailing partials.
    // Trailing keys are monotone across the warp (sorted segs), so the
    // strided conditional add is an exact segmented reduction.
    int seg = sg[T_PER_THREAD - 1];
    #pragma unroll
    for (int off = 4; off <= 16; off <<= 1) {
        int   oseg = __shfl_down_sync(0xffffffffu, seg, off);
        float ox   = __shfl_down_sync(0xffffffffu, acc.x, off);
        float oy   = __shfl_down_sync(0xffffffffu, acc.y, off);
        float oz   = __shfl_down_sync(0xffffffffu, acc.z, off);
        float ow   = __shfl_down_sync(0xffffffffu, acc.w, off);
        if ((lane + off) < 32 && oseg == seg) {
            acc.x += ox; acc.y += oy; acc.z += oz; acc.w += ow;
        }
    }

    const int  pseg = __shfl_up_sync(0xffffffffu, seg, 4);
    const bool head = (tokGroup == 0) || (pseg != seg);

    if (head) {
        red_add_v4(out + (size_t)seg * DIM + slot * 4, acc);
    }
}

extern "C" void kernel_launch(void* const* d_in, const int* in_sizes, int n_in,
                              void* d_out, int out_size) {
    const int*   ids     = (const int*)  d_in[0];
    const float* ratings = (const float*)d_in[1];
    const int*   segs    = (const int*)  d_in[2];
    // d_in[3] = batch_size scalar (unused)
    const float* weight  = (const float*)d_in[4];
    const float* bias    = (const float*)d_in[5];
    float*       out     = (float*)d_out;

    const int n = in_sizes[0];

    // Init output with bias (vectorized).
    {
        int quads   = out_size / 4;
        int threads = 256;
        int blocks  = (quads + threads - 1) / threads;
        fl_init_out<<<blocks, threads>>>((float4*)out, (const float4*)bias, quads);
    }

    // Main gather + segmented reduce: 32 tokens per warp, 16 warps per block.
    {
        int warps   = (n + 31) / 32;
        int threads = 512;
        int blocks  = (warps + 15) / 16;
        fl_main<<<blocks, threads>>>(ids, ratings, segs,
                                     (const float4*)weight, out, n);
    }
}